// round 4
// baseline (speedup 1.0000x reference)
#include <cuda_runtime.h>
#include <cuda_bf16.h>
#include <stdint.h>

#define NP   120000
#define INC  256
#define MIDC 64
#define OUTC 256
#define KNB  27
#define EPSV 1e-5f

// ---------------- scratch (device globals; no allocs allowed) ----------------
__device__ float    g_y1[NP * MIDC];          // x@W1 raw
__device__ unsigned g_h1[NP * MIDC];          // tf32 bits of relu(bn1(y1))
__device__ float    g_h2[NP * MIDC];          // einsum output raw
__device__ float    g_hb[NP * MIDC];          // relu(bn2(h2))
__device__ unsigned g_W3t[KNB * MIDC * MIDC]; // tf32 bits of W3
__device__ float g_sum1[MIDC], g_ss1[MIDC], g_sc1[MIDC], g_sh1[MIDC];
__device__ float g_sum2[MIDC], g_ss2[MIDC], g_sc2[MIDC], g_sh2[MIDC];
__device__ float g_svec[MIDC];
__device__ float g_M[MIDC * MIDC];
__device__ float g_sc3[OUTC], g_sh3[OUTC];

__device__ __forceinline__ unsigned tf32_of(float f) {
    unsigned u;
    asm("cvt.rna.tf32.f32 %0, %1;" : "=r"(u) : "f"(f));
    return u;
}

__device__ __forceinline__ void mma_tf32(float* d, const unsigned* a, const unsigned* b) {
    asm volatile(
        "mma.sync.aligned.m16n8k8.row.col.f32.tf32.tf32.f32 "
        "{%0,%1,%2,%3}, {%4,%5,%6,%7}, {%8,%9}, {%0,%1,%2,%3};"
        : "+f"(d[0]), "+f"(d[1]), "+f"(d[2]), "+f"(d[3])
        : "r"(a[0]), "r"(a[1]), "r"(a[2]), "r"(a[3]), "r"(b[0]), "r"(b[1]));
}

// ---------------- zero accumulators ----------------
__global__ void k_zero() {
    int i = blockIdx.x * blockDim.x + threadIdx.x;
    if (i < MIDC) {
        g_sum1[i] = 0.f; g_ss1[i] = 0.f;
        g_sum2[i] = 0.f; g_ss2[i] = 0.f;
        g_svec[i] = 0.f;
    }
    if (i < MIDC * MIDC) g_M[i] = 0.f;
}

// ---------------- GEMM1: y1 = x @ W1  [N,256]x[256,64] fp32 SIMT ----------------
__global__ void __launch_bounds__(256) k_gemm1(const float* __restrict__ x,
                                               const float* __restrict__ W1) {
    __shared__ float As[64][64];
    __shared__ float Bs[64][68];
    int t = threadIdx.x;
    int tx = t & 15, ty = t >> 4;
    int lc = t & 63, lr = t >> 6;
    int rb = blockIdx.x * 64;
    float acc[4][4] = {};

    for (int k0 = 0; k0 < INC; k0 += 64) {
        __syncthreads();
        #pragma unroll
        for (int j = 0; j < 16; j++) {
            int r = lr + 4 * j;
            As[r][lc] = x[(size_t)(rb + r) * INC + k0 + lc];
            Bs[r][lc] = W1[(size_t)(k0 + r) * MIDC + lc];
        }
        __syncthreads();
        #pragma unroll 8
        for (int c = 0; c < 64; c++) {
            float4 bv = *(const float4*)&Bs[c][4 * tx];
            float a0 = As[4 * ty + 0][c];
            float a1 = As[4 * ty + 1][c];
            float a2 = As[4 * ty + 2][c];
            float a3 = As[4 * ty + 3][c];
            acc[0][0] = fmaf(a0, bv.x, acc[0][0]); acc[0][1] = fmaf(a0, bv.y, acc[0][1]);
            acc[0][2] = fmaf(a0, bv.z, acc[0][2]); acc[0][3] = fmaf(a0, bv.w, acc[0][3]);
            acc[1][0] = fmaf(a1, bv.x, acc[1][0]); acc[1][1] = fmaf(a1, bv.y, acc[1][1]);
            acc[1][2] = fmaf(a1, bv.z, acc[1][2]); acc[1][3] = fmaf(a1, bv.w, acc[1][3]);
            acc[2][0] = fmaf(a2, bv.x, acc[2][0]); acc[2][1] = fmaf(a2, bv.y, acc[2][1]);
            acc[2][2] = fmaf(a2, bv.z, acc[2][2]); acc[2][3] = fmaf(a2, bv.w, acc[2][3]);
            acc[3][0] = fmaf(a3, bv.x, acc[3][0]); acc[3][1] = fmaf(a3, bv.y, acc[3][1]);
            acc[3][2] = fmaf(a3, bv.z, acc[3][2]); acc[3][3] = fmaf(a3, bv.w, acc[3][3]);
        }
    }
    #pragma unroll
    for (int i = 0; i < 4; i++) {
        float4 v = make_float4(acc[i][0], acc[i][1], acc[i][2], acc[i][3]);
        *(float4*)&g_y1[(size_t)(rb + 4 * ty + i) * MIDC + 4 * tx] = v;
    }
}

// ---------------- per-channel sum / sumsq over [N,64] ----------------
__global__ void __launch_bounds__(256) k_stats(int which) {
    __shared__ float s_s[4][MIDC], s_q[4][MIDC];
    const float* __restrict__ src = which ? g_h2 : g_y1;
    float* sumO = which ? g_sum2 : g_sum1;
    float* ssO  = which ? g_ss2  : g_ss1;
    int t = threadIdx.x;
    int c = t & 63, rw = t >> 6;
    size_t r0 = (size_t)blockIdx.x * 250;  // 480 * 250 = 120000
    float s = 0.f, q = 0.f;
    for (int r = rw; r < 250; r += 4) {
        float v = src[(r0 + r) * MIDC + c];
        s += v; q = fmaf(v, v, q);
    }
    s_s[rw][c] = s; s_q[rw][c] = q;
    __syncthreads();
    if (t < MIDC) {
        float S = s_s[0][t] + s_s[1][t] + s_s[2][t] + s_s[3][t];
        float Q = s_q[0][t] + s_q[1][t] + s_q[2][t] + s_q[3][t];
        atomicAdd(&sumO[t], S);
        atomicAdd(&ssO[t], Q);
    }
}

// ---------------- finalize BN1/BN2 params ----------------
__global__ void k_finalize(int which, const float* __restrict__ g, const float* __restrict__ b) {
    int c = threadIdx.x;
    if (c >= MIDC) return;
    const float* sum = which ? g_sum2 : g_sum1;
    const float* ss  = which ? g_ss2  : g_ss1;
    float* sc = which ? g_sc2 : g_sc1;
    float* sh = which ? g_sh2 : g_sh1;
    float m = sum[c] * (1.f / NP);
    float v = ss[c] * (1.f / NP) - m * m;
    float s = g[c] * rsqrtf(v + EPSV);
    sc[c] = s;
    sh[c] = b[c] - m * s;
}

// ---------------- h1 = tf32(relu(bn1(y1))) ----------------
__global__ void __launch_bounds__(256) k_bn1() {
    int i = blockIdx.x * blockDim.x + threadIdx.x;  // float4 index; 7500*256 exact
    int cf = (i & 15) * 4;
    float4 v = ((const float4*)g_y1)[i];
    uint4 o;
    o.x = tf32_of(fmaxf(fmaf(v.x, g_sc1[cf + 0], g_sh1[cf + 0]), 0.f));
    o.y = tf32_of(fmaxf(fmaf(v.y, g_sc1[cf + 1], g_sh1[cf + 1]), 0.f));
    o.z = tf32_of(fmaxf(fmaf(v.z, g_sc1[cf + 2], g_sh1[cf + 2]), 0.f));
    o.w = tf32_of(fmaxf(fmaf(v.w, g_sc1[cf + 3], g_sh1[cf + 3]), 0.f));
    ((uint4*)g_h1)[i] = o;
}

// ---------------- W3 -> tf32 ----------------
__global__ void k_w3(const float* __restrict__ W3) {
    int i = blockIdx.x * blockDim.x + threadIdx.x;  // 432*256 = 110592 exact
    g_W3t[i] = tf32_of(W3[i]);
}

// ---------------- einsum via TF32 mma: h2 = sum_k h1[nbr[:,k]] @ W3[k] ----------------
// 1250 blocks x 96-point tiles. 8 warps: 2 row-groups(48 rows) x 4 col-groups(16 cols).
// Static smem only (44544 B < 48 KB) -> no cudaFuncSetAttribute needed.
__global__ void __launch_bounds__(256) k_einsum(const int* __restrict__ nbr) {
    __shared__ unsigned As[96][68];
    __shared__ unsigned Bs[64][72];

    int t = threadIdx.x;
    int rb = blockIdx.x * 96;
    int lane = t & 31, w = t >> 5;
    int wr = (w & 1) * 48;    // warp row base
    int wc = (w >> 1) * 16;   // warp col base
    int f = t & 15;           // uint4 column within a 64-wide row
    int rbase = t >> 4;       // 0..15
    const uint4* h1v = (const uint4*)g_h1;
    const uint4* w3v = (const uint4*)g_W3t;
    int qr = lane >> 2, qk = lane & 3;

    float acc[3][2][4] = {};

    #pragma unroll 1
    for (int k = 0; k < KNB; k++) {
        __syncthreads();
        // B tile: W3[k] (64x64)
        #pragma unroll
        for (int j = 0; j < 4; j++) {
            int c = rbase + 16 * j;
            uint4 v = w3v[(k * 64 + c) * 16 + f];
            *(uint4*)&Bs[c][4 * f] = v;
        }
        // A tile: gather 96 rows of h1 (16 lanes/row -> coalesced 256B per row)
        #pragma unroll
        for (int j = 0; j < 6; j++) {
            int r = rbase + 16 * j;
            int src = nbr[(size_t)(rb + r) * KNB + k];  // broadcast among 16 lanes
            uint4 v = h1v[(size_t)src * 16 + f];
            *(uint4*)&As[r][4 * f] = v;
        }
        __syncthreads();
        #pragma unroll
        for (int kk = 0; kk < 64; kk += 8) {
            unsigned b[2][2];
            #pragma unroll
            for (int nt = 0; nt < 2; nt++) {
                int col = wc + nt * 8 + qr;
                b[nt][0] = Bs[kk + qk][col];
                b[nt][1] = Bs[kk + qk + 4][col];
            }
            #pragma unroll
            for (int mt = 0; mt < 3; mt++) {
                unsigned a[4];
                int ar = wr + mt * 16 + qr;
                a[0] = As[ar][kk + qk];
                a[1] = As[ar + 8][kk + qk];
                a[2] = As[ar][kk + qk + 4];
                a[3] = As[ar + 8][kk + qk + 4];
                #pragma unroll
                for (int nt = 0; nt < 2; nt++) mma_tf32(acc[mt][nt], a, b[nt]);
            }
        }
    }
    // epilogue: c0/c1 at (row, 2*qk+{0,1}), c2/c3 at row+8
    #pragma unroll
    for (int mt = 0; mt < 3; mt++) {
        int r0 = rb + wr + mt * 16 + qr;
        #pragma unroll
        for (int nt = 0; nt < 2; nt++) {
            int c0 = wc + nt * 8 + 2 * qk;
            *(float2*)&g_h2[(size_t)r0 * MIDC + c0] = make_float2(acc[mt][nt][0], acc[mt][nt][1]);
            *(float2*)&g_h2[(size_t)(r0 + 8) * MIDC + c0] = make_float2(acc[mt][nt][2], acc[mt][nt][3]);
        }
    }
}

// ---------------- h = relu(bn2(h2)); s += colsum(h); M += h^T h ----------------
__global__ void __launch_bounds__(256) k_moment() {
    __shared__ float Hs[64][68];
    int t = threadIdx.x;
    int tx = t & 15, ty = t >> 4;
    size_t rb = (size_t)blockIdx.x * 64;
    for (int i = t; i < 64 * 64; i += 256) {
        int r = i >> 6, c = i & 63;
        float v = g_h2[(rb + r) * MIDC + c];
        float h = fmaxf(fmaf(v, g_sc2[c], g_sh2[c]), 0.f);
        Hs[r][c] = h;
        g_hb[(rb + r) * MIDC + c] = h;
    }
    __syncthreads();
    if (t < 64) {
        float s = 0.f;
        #pragma unroll 8
        for (int r = 0; r < 64; r++) s += Hs[r][t];
        atomicAdd(&g_svec[t], s);
    }
    float acc[4][4] = {};
    #pragma unroll 8
    for (int r = 0; r < 64; r++) {
        float4 bv = *(const float4*)&Hs[r][4 * tx];
        float a0 = Hs[r][4 * ty + 0];
        float a1 = Hs[r][4 * ty + 1];
        float a2 = Hs[r][4 * ty + 2];
        float a3 = Hs[r][4 * ty + 3];
        acc[0][0] = fmaf(a0, bv.x, acc[0][0]); acc[0][1] = fmaf(a0, bv.y, acc[0][1]);
        acc[0][2] = fmaf(a0, bv.z, acc[0][2]); acc[0][3] = fmaf(a0, bv.w, acc[0][3]);
        acc[1][0] = fmaf(a1, bv.x, acc[1][0]); acc[1][1] = fmaf(a1, bv.y, acc[1][1]);
        acc[1][2] = fmaf(a1, bv.z, acc[1][2]); acc[1][3] = fmaf(a1, bv.w, acc[1][3]);
        acc[2][0] = fmaf(a2, bv.x, acc[2][0]); acc[2][1] = fmaf(a2, bv.y, acc[2][1]);
        acc[2][2] = fmaf(a2, bv.z, acc[2][2]); acc[2][3] = fmaf(a2, bv.w, acc[2][3]);
        acc[3][0] = fmaf(a3, bv.x, acc[3][0]); acc[3][1] = fmaf(a3, bv.y, acc[3][1]);
        acc[3][2] = fmaf(a3, bv.z, acc[3][2]); acc[3][3] = fmaf(a3, bv.w, acc[3][3]);
    }
    #pragma unroll
    for (int i = 0; i < 4; i++)
        #pragma unroll
        for (int j = 0; j < 4; j++)
            atomicAdd(&g_M[(4 * ty + i) * MIDC + 4 * tx + j], acc[i][j]);
}

// ---------------- BN3 params from s, M: one warp per output channel ----------------
__global__ void __launch_bounds__(256) k_finalize3(const float* __restrict__ W2,
                                                   const float* __restrict__ g3,
                                                   const float* __restrict__ b3) {
    __shared__ float Ms[64][65];
    __shared__ float sv[64];
    int t = threadIdx.x;
    for (int i = t; i < 64 * 64; i += 256) Ms[i >> 6][i & 63] = g_M[i] * (1.f / NP);
    if (t < 64) sv[t] = g_svec[t] * (1.f / NP);
    __syncthreads();

    int lane = t & 31, w = t >> 5;
    int c = blockIdx.x * 8 + w;  // 32 blocks * 8 warps = 256 channels
    float mean_p = 0.f, e2_p = 0.f;
    #pragma unroll
    for (int half = 0; half < 2; half++) {
        int bcol = lane + 32 * half;
        float wb = W2[(size_t)bcol * OUTC + c];
        mean_p = fmaf(sv[bcol], wb, mean_p);
        float p = 0.f;
        #pragma unroll 8
        for (int a = 0; a < 64; a++) {
            float wa = W2[(size_t)a * OUTC + c];
            p = fmaf(Ms[a][bcol], wa, p);
        }
        e2_p = fmaf(wb, p, e2_p);
    }
    #pragma unroll
    for (int off = 16; off > 0; off >>= 1) {
        mean_p += __shfl_xor_sync(0xFFFFFFFFu, mean_p, off);
        e2_p   += __shfl_xor_sync(0xFFFFFFFFu, e2_p, off);
    }
    if (lane == 0) {
        float var = e2_p - mean_p * mean_p;
        float s = g3[c] * rsqrtf(var + EPSV);
        g_sc3[c] = s;
        g_sh3[c] = b3[c] - mean_p * s;
    }
}

// ---------------- GEMM3 fused: out = relu(bn3(h @ W2) + x) ----------------
__global__ void __launch_bounds__(256) k_gemm3f(const float* __restrict__ x,
                                                const float* __restrict__ W2,
                                                float* __restrict__ out) {
    __shared__ float Hs[64][68];
    int t = threadIdx.x;
    int tx = t & 15, ty = t >> 4;
    size_t rb = (size_t)blockIdx.x * 64;
    for (int i = t; i < 64 * 64; i += 256) {
        int r = i >> 6, c = i & 63;
        Hs[r][c] = g_hb[(rb + r) * MIDC + c];
    }
    __syncthreads();

    float acc[4][16] = {};
    #pragma unroll 4
    for (int k = 0; k < 64; k++) {
        float a0 = Hs[4 * ty + 0][k];
        float a1 = Hs[4 * ty + 1][k];
        float a2 = Hs[4 * ty + 2][k];
        float a3 = Hs[4 * ty + 3][k];
        const float4* wrow = (const float4*)&W2[(size_t)k * OUTC + 16 * tx];
        #pragma unroll
        for (int jj = 0; jj < 4; jj++) {
            float4 bv = wrow[jj];
            acc[0][4*jj+0] = fmaf(a0, bv.x, acc[0][4*jj+0]);
            acc[0][4*jj+1] = fmaf(a0, bv.y, acc[0][4*jj+1]);
            acc[0][4*jj+2] = fmaf(a0, bv.z, acc[0][4*jj+2]);
            acc[0][4*jj+3] = fmaf(a0, bv.w, acc[0][4*jj+3]);
            acc[1][4*jj+0] = fmaf(a1, bv.x, acc[1][4*jj+0]);
            acc[1][4*jj+1] = fmaf(a1, bv.y, acc[1][4*jj+1]);
            acc[1][4*jj+2] = fmaf(a1, bv.z, acc[1][4*jj+2]);
            acc[1][4*jj+3] = fmaf(a1, bv.w, acc[1][4*jj+3]);
            acc[2][4*jj+0] = fmaf(a2, bv.x, acc[2][4*jj+0]);
            acc[2][4*jj+1] = fmaf(a2, bv.y, acc[2][4*jj+1]);
            acc[2][4*jj+2] = fmaf(a2, bv.z, acc[2][4*jj+2]);
            acc[2][4*jj+3] = fmaf(a2, bv.w, acc[2][4*jj+3]);
            acc[3][4*jj+0] = fmaf(a3, bv.x, acc[3][4*jj+0]);
            acc[3][4*jj+1] = fmaf(a3, bv.y, acc[3][4*jj+1]);
            acc[3][4*jj+2] = fmaf(a3, bv.z, acc[3][4*jj+2]);
            acc[3][4*jj+3] = fmaf(a3, bv.w, acc[3][4*jj+3]);
        }
    }

    float sc[16], sh[16];
    #pragma unroll
    for (int j = 0; j < 16; j++) {
        sc[j] = g_sc3[16 * tx + j];
        sh[j] = g_sh3[16 * tx + j];
    }
    #pragma unroll
    for (int i = 0; i < 4; i++) {
        size_t r = rb + 4 * ty + i;
        #pragma unroll
        for (int jj = 0; jj < 4; jj++) {
            float4 xa = *(const float4*)&x[r * OUTC + 16 * tx + 4 * jj];
            float4 o;
            o.x = fmaxf(fmaf(acc[i][4*jj+0], sc[4*jj+0], sh[4*jj+0]) + xa.x, 0.f);
            o.y = fmaxf(fmaf(acc[i][4*jj+1], sc[4*jj+1], sh[4*jj+1]) + xa.y, 0.f);
            o.z = fmaxf(fmaf(acc[i][4*jj+2], sc[4*jj+2], sh[4*jj+2]) + xa.z, 0.f);
            o.w = fmaxf(fmaf(acc[i][4*jj+3], sc[4*jj+3], sh[4*jj+3]) + xa.w, 0.f);
            *(float4*)&out[r * OUTC + 16 * tx + 4 * jj] = o;
        }
    }
}

// ---------------- host launch ----------------
extern "C" void kernel_launch(void* const* d_in, const int* in_sizes, int n_in,
                              void* d_out, int out_size) {
    const float* x    = (const float*)d_in[0];
    const int*   nbr  = (const int*)  d_in[1];
    const float* W1   = (const float*)d_in[2];
    const float* W3   = (const float*)d_in[3];
    const float* W2   = (const float*)d_in[4];
    const float* g1   = (const float*)d_in[5];
    const float* b1   = (const float*)d_in[6];
    const float* g2   = (const float*)d_in[7];
    const float* b2   = (const float*)d_in[8];
    const float* g3   = (const float*)d_in[9];
    const float* b3   = (const float*)d_in[10];
    float* out = (float*)d_out;

    k_zero<<<16, 256>>>();
    k_gemm1<<<NP / 64, 256>>>(x, W1);
    k_stats<<<480, 256>>>(0);
    k_finalize<<<1, 64>>>(0, g1, b1);
    k_bn1<<<NP * MIDC / 4 / 256, 256>>>();
    k_w3<<<KNB * MIDC * MIDC / 256, 256>>>(W3);
    k_einsum<<<NP / 96, 256>>>(nbr);
    k_stats<<<480, 256>>>(1);
    k_finalize<<<1, 64>>>(1, g2, b2);
    k_moment<<<NP / 64, 256>>>();
    k_finalize3<<<32, 256>>>(W2, g3, b3);
    k_gemm3f<<<NP / 64, 256>>>(x, W2, out);
}

// round 5
// speedup vs baseline: 1.5901x; 1.5901x over previous
#include <cuda_runtime.h>
#include <cuda_bf16.h>
#include <stdint.h>

#define NP   120000
#define INC  256
#define MIDC 64
#define OUTC 256
#define KNB  27
#define EPSV 1e-5f

// ---------------- scratch (device globals; no allocs allowed) ----------------
__device__ float    g_y1[NP * MIDC];          // x@W1 raw (fp32, for bn1 stats application)
__device__ unsigned g_h1[NP * MIDC];          // tf32 bits of relu(bn1(y1))
__device__ float    g_h2[NP * MIDC];          // einsum output raw
__device__ unsigned g_hbt[NP * MIDC];         // tf32 bits of relu(bn2(h2))
__device__ unsigned g_W3t[KNB * MIDC * MIDC]; // tf32 bits of W3
__device__ unsigned g_W2t[MIDC * OUTC];       // tf32 bits of W2
__device__ float g_sum1[MIDC], g_ss1[MIDC], g_sc1[MIDC], g_sh1[MIDC];
__device__ float g_sum2[MIDC], g_ss2[MIDC], g_sc2[MIDC], g_sh2[MIDC];
__device__ float g_svec[MIDC];
__device__ float g_M[MIDC * MIDC];
__device__ float g_sc3[OUTC], g_sh3[OUTC];

__device__ __forceinline__ unsigned tf32_of(float f) {
    unsigned u;
    asm("cvt.rna.tf32.f32 %0, %1;" : "=r"(u) : "f"(f));
    return u;
}

__device__ __forceinline__ void mma_tf32(float* d, const unsigned* a, const unsigned* b) {
    asm volatile(
        "mma.sync.aligned.m16n8k8.row.col.f32.tf32.tf32.f32 "
        "{%0,%1,%2,%3}, {%4,%5,%6,%7}, {%8,%9}, {%0,%1,%2,%3};"
        : "+f"(d[0]), "+f"(d[1]), "+f"(d[2]), "+f"(d[3])
        : "r"(a[0]), "r"(a[1]), "r"(a[2]), "r"(a[3]), "r"(b[0]), "r"(b[1]));
}

// ---------------- zero accumulators ----------------
__global__ void k_zero() {
    int i = blockIdx.x * blockDim.x + threadIdx.x;
    if (i < MIDC) {
        g_sum1[i] = 0.f; g_ss1[i] = 0.f;
        g_sum2[i] = 0.f; g_ss2[i] = 0.f;
        g_svec[i] = 0.f;
    }
    if (i < MIDC * MIDC) g_M[i] = 0.f;
}

// ---------------- weight conversion: W3 and W2 -> tf32 ----------------
__global__ void k_wcvt(const float* __restrict__ W3, const float* __restrict__ W2) {
    int i = blockIdx.x * blockDim.x + threadIdx.x;  // 496*256 = 126976 exact
    if (i < KNB * MIDC * MIDC) g_W3t[i] = tf32_of(W3[i]);
    else {
        int j = i - KNB * MIDC * MIDC;  // < 16384
        g_W2t[j] = tf32_of(W2[j]);
    }
}

// ---------------- GEMM1 (TF32 mma): y1 = x @ W1, fused BN1 stats ----------------
// 1250 blocks x 96-row tiles. 8 warps: 2 row-groups(48) x 4 col-groups(16).
__global__ void __launch_bounds__(256) k_gemm1(const float* __restrict__ x,
                                               const float* __restrict__ W1) {
    __shared__ unsigned As[96][68];
    __shared__ unsigned Bs[64][72];
    __shared__ float s_sum[MIDC], s_ss[MIDC];

    int t = threadIdx.x;
    if (t < MIDC) { s_sum[t] = 0.f; s_ss[t] = 0.f; }

    int rb = blockIdx.x * 96;
    int lane = t & 31, w = t >> 5;
    int wr = (w & 1) * 48;
    int wc = (w >> 1) * 16;
    int f = t & 15;
    int rbase = t >> 4;
    int qr = lane >> 2, qk = lane & 3;

    float acc[3][2][4] = {};

    for (int k0 = 0; k0 < INC; k0 += 64) {
        __syncthreads();
        // B: W1 chunk [64 x 64]
        #pragma unroll
        for (int j = 0; j < 4; j++) {
            int c = rbase + 16 * j;
            float4 v = *(const float4*)&W1[(size_t)(k0 + c) * MIDC + 4 * f];
            Bs[c][4 * f + 0] = tf32_of(v.x);
            Bs[c][4 * f + 1] = tf32_of(v.y);
            Bs[c][4 * f + 2] = tf32_of(v.z);
            Bs[c][4 * f + 3] = tf32_of(v.w);
        }
        // A: x chunk [96 x 64]
        #pragma unroll
        for (int j = 0; j < 6; j++) {
            int r = rbase + 16 * j;
            float4 v = *(const float4*)&x[(size_t)(rb + r) * INC + k0 + 4 * f];
            As[r][4 * f + 0] = tf32_of(v.x);
            As[r][4 * f + 1] = tf32_of(v.y);
            As[r][4 * f + 2] = tf32_of(v.z);
            As[r][4 * f + 3] = tf32_of(v.w);
        }
        __syncthreads();
        #pragma unroll
        for (int kk = 0; kk < 64; kk += 8) {
            unsigned b[2][2];
            #pragma unroll
            for (int nt = 0; nt < 2; nt++) {
                int col = wc + nt * 8 + qr;
                b[nt][0] = Bs[kk + qk][col];
                b[nt][1] = Bs[kk + qk + 4][col];
            }
            #pragma unroll
            for (int mt = 0; mt < 3; mt++) {
                unsigned a[4];
                int ar = wr + mt * 16 + qr;
                a[0] = As[ar][kk + qk];
                a[1] = As[ar + 8][kk + qk];
                a[2] = As[ar][kk + qk + 4];
                a[3] = As[ar + 8][kk + qk + 4];
                #pragma unroll
                for (int nt = 0; nt < 2; nt++) mma_tf32(acc[mt][nt], a, b[nt]);
            }
        }
    }
    // epilogue: write y1 + block stats
    #pragma unroll
    for (int mt = 0; mt < 3; mt++) {
        int r0 = rb + wr + mt * 16 + qr;
        #pragma unroll
        for (int nt = 0; nt < 2; nt++) {
            int c0 = wc + nt * 8 + 2 * qk;
            *(float2*)&g_y1[(size_t)r0 * MIDC + c0] = make_float2(acc[mt][nt][0], acc[mt][nt][1]);
            *(float2*)&g_y1[(size_t)(r0 + 8) * MIDC + c0] = make_float2(acc[mt][nt][2], acc[mt][nt][3]);
        }
    }
    #pragma unroll
    for (int nt = 0; nt < 2; nt++) {
        int c0 = wc + nt * 8 + 2 * qk;
        float se = 0.f, qe = 0.f, so = 0.f, qo = 0.f;
        #pragma unroll
        for (int mt = 0; mt < 3; mt++) {
            se += acc[mt][nt][0] + acc[mt][nt][2];
            qe += acc[mt][nt][0] * acc[mt][nt][0] + acc[mt][nt][2] * acc[mt][nt][2];
            so += acc[mt][nt][1] + acc[mt][nt][3];
            qo += acc[mt][nt][1] * acc[mt][nt][1] + acc[mt][nt][3] * acc[mt][nt][3];
        }
        atomicAdd(&s_sum[c0], se);     atomicAdd(&s_ss[c0], qe);
        atomicAdd(&s_sum[c0 + 1], so); atomicAdd(&s_ss[c0 + 1], qo);
    }
    __syncthreads();
    if (t < MIDC) {
        atomicAdd(&g_sum1[t], s_sum[t]);
        atomicAdd(&g_ss1[t], s_ss[t]);
    }
}

// ---------------- per-channel sum / sumsq over h2 [N,64] ----------------
__global__ void __launch_bounds__(256) k_stats2() {
    __shared__ float s_s[4][MIDC], s_q[4][MIDC];
    int t = threadIdx.x;
    int c = t & 63, rw = t >> 6;
    size_t r0 = (size_t)blockIdx.x * 250;  // 480 * 250 = 120000
    float s = 0.f, q = 0.f;
    for (int r = rw; r < 250; r += 4) {
        float v = g_h2[(r0 + r) * MIDC + c];
        s += v; q = fmaf(v, v, q);
    }
    s_s[rw][c] = s; s_q[rw][c] = q;
    __syncthreads();
    if (t < MIDC) {
        float S = s_s[0][t] + s_s[1][t] + s_s[2][t] + s_s[3][t];
        float Q = s_q[0][t] + s_q[1][t] + s_q[2][t] + s_q[3][t];
        atomicAdd(&g_sum2[t], S);
        atomicAdd(&g_ss2[t], Q);
    }
}

// ---------------- finalize BN1/BN2 params ----------------
__global__ void k_finalize(int which, const float* __restrict__ g, const float* __restrict__ b) {
    int c = threadIdx.x;
    if (c >= MIDC) return;
    const float* sum = which ? g_sum2 : g_sum1;
    const float* ss  = which ? g_ss2  : g_ss1;
    float* sc = which ? g_sc2 : g_sc1;
    float* sh = which ? g_sh2 : g_sh1;
    float m = sum[c] * (1.f / NP);
    float v = ss[c] * (1.f / NP) - m * m;
    float s = g[c] * rsqrtf(v + EPSV);
    sc[c] = s;
    sh[c] = b[c] - m * s;
}

// ---------------- h1 = tf32(relu(bn1(y1))) ----------------
__global__ void __launch_bounds__(256) k_bn1() {
    int i = blockIdx.x * blockDim.x + threadIdx.x;  // float4 index; 7500*256 exact
    int cf = (i & 15) * 4;
    float4 v = ((const float4*)g_y1)[i];
    uint4 o;
    o.x = tf32_of(fmaxf(fmaf(v.x, g_sc1[cf + 0], g_sh1[cf + 0]), 0.f));
    o.y = tf32_of(fmaxf(fmaf(v.y, g_sc1[cf + 1], g_sh1[cf + 1]), 0.f));
    o.z = tf32_of(fmaxf(fmaf(v.z, g_sc1[cf + 2], g_sh1[cf + 2]), 0.f));
    o.w = tf32_of(fmaxf(fmaf(v.w, g_sc1[cf + 3], g_sh1[cf + 3]), 0.f));
    ((uint4*)g_h1)[i] = o;
}

// ---------------- einsum via TF32 mma: h2 = sum_k h1[nbr[:,k]] @ W3[k] ----------------
__global__ void __launch_bounds__(256) k_einsum(const int* __restrict__ nbr) {
    __shared__ unsigned As[96][68];
    __shared__ unsigned Bs[64][72];

    int t = threadIdx.x;
    int rb = blockIdx.x * 96;
    int lane = t & 31, w = t >> 5;
    int wr = (w & 1) * 48;
    int wc = (w >> 1) * 16;
    int f = t & 15;
    int rbase = t >> 4;
    const uint4* h1v = (const uint4*)g_h1;
    const uint4* w3v = (const uint4*)g_W3t;
    int qr = lane >> 2, qk = lane & 3;

    float acc[3][2][4] = {};

    #pragma unroll 1
    for (int k = 0; k < KNB; k++) {
        __syncthreads();
        #pragma unroll
        for (int j = 0; j < 4; j++) {
            int c = rbase + 16 * j;
            uint4 v = w3v[(k * 64 + c) * 16 + f];
            *(uint4*)&Bs[c][4 * f] = v;
        }
        #pragma unroll
        for (int j = 0; j < 6; j++) {
            int r = rbase + 16 * j;
            int src = nbr[(size_t)(rb + r) * KNB + k];
            uint4 v = h1v[(size_t)src * 16 + f];
            *(uint4*)&As[r][4 * f] = v;
        }
        __syncthreads();
        #pragma unroll
        for (int kk = 0; kk < 64; kk += 8) {
            unsigned b[2][2];
            #pragma unroll
            for (int nt = 0; nt < 2; nt++) {
                int col = wc + nt * 8 + qr;
                b[nt][0] = Bs[kk + qk][col];
                b[nt][1] = Bs[kk + qk + 4][col];
            }
            #pragma unroll
            for (int mt = 0; mt < 3; mt++) {
                unsigned a[4];
                int ar = wr + mt * 16 + qr;
                a[0] = As[ar][kk + qk];
                a[1] = As[ar + 8][kk + qk];
                a[2] = As[ar][kk + qk + 4];
                a[3] = As[ar + 8][kk + qk + 4];
                #pragma unroll
                for (int nt = 0; nt < 2; nt++) mma_tf32(acc[mt][nt], a, b[nt]);
            }
        }
    }
    #pragma unroll
    for (int mt = 0; mt < 3; mt++) {
        int r0 = rb + wr + mt * 16 + qr;
        #pragma unroll
        for (int nt = 0; nt < 2; nt++) {
            int c0 = wc + nt * 8 + 2 * qk;
            *(float2*)&g_h2[(size_t)r0 * MIDC + c0] = make_float2(acc[mt][nt][0], acc[mt][nt][1]);
            *(float2*)&g_h2[(size_t)(r0 + 8) * MIDC + c0] = make_float2(acc[mt][nt][2], acc[mt][nt][3]);
        }
    }
}

// ---------------- h = relu(bn2(h2)) -> tf32 bits; s += colsum(h); M += h^T h ----------------
__global__ void __launch_bounds__(256) k_moment() {
    __shared__ float Hs[64][68];
    int t = threadIdx.x;
    int tx = t & 15, ty = t >> 4;
    size_t rb = (size_t)blockIdx.x * 64;
    for (int i = t; i < 64 * 64; i += 256) {
        int r = i >> 6, c = i & 63;
        float v = g_h2[(rb + r) * MIDC + c];
        float h = fmaxf(fmaf(v, g_sc2[c], g_sh2[c]), 0.f);
        Hs[r][c] = h;
        g_hbt[(rb + r) * MIDC + c] = tf32_of(h);
    }
    __syncthreads();
    if (t < 64) {
        float s = 0.f;
        #pragma unroll 8
        for (int r = 0; r < 64; r++) s += Hs[r][t];
        atomicAdd(&g_svec[t], s);
    }
    float acc[4][4] = {};
    #pragma unroll 8
    for (int r = 0; r < 64; r++) {
        float4 bv = *(const float4*)&Hs[r][4 * tx];
        float a0 = Hs[r][4 * ty + 0];
        float a1 = Hs[r][4 * ty + 1];
        float a2 = Hs[r][4 * ty + 2];
        float a3 = Hs[r][4 * ty + 3];
        acc[0][0] = fmaf(a0, bv.x, acc[0][0]); acc[0][1] = fmaf(a0, bv.y, acc[0][1]);
        acc[0][2] = fmaf(a0, bv.z, acc[0][2]); acc[0][3] = fmaf(a0, bv.w, acc[0][3]);
        acc[1][0] = fmaf(a1, bv.x, acc[1][0]); acc[1][1] = fmaf(a1, bv.y, acc[1][1]);
        acc[1][2] = fmaf(a1, bv.z, acc[1][2]); acc[1][3] = fmaf(a1, bv.w, acc[1][3]);
        acc[2][0] = fmaf(a2, bv.x, acc[2][0]); acc[2][1] = fmaf(a2, bv.y, acc[2][1]);
        acc[2][2] = fmaf(a2, bv.z, acc[2][2]); acc[2][3] = fmaf(a2, bv.w, acc[2][3]);
        acc[3][0] = fmaf(a3, bv.x, acc[3][0]); acc[3][1] = fmaf(a3, bv.y, acc[3][1]);
        acc[3][2] = fmaf(a3, bv.z, acc[3][2]); acc[3][3] = fmaf(a3, bv.w, acc[3][3]);
    }
    #pragma unroll
    for (int i = 0; i < 4; i++)
        #pragma unroll
        for (int j = 0; j < 4; j++)
            atomicAdd(&g_M[(4 * ty + i) * MIDC + 4 * tx + j], acc[i][j]);
}

// ---------------- BN3 params from s, M ----------------
__global__ void __launch_bounds__(256) k_finalize3(const float* __restrict__ W2,
                                                   const float* __restrict__ g3,
                                                   const float* __restrict__ b3) {
    __shared__ float Ms[64][65];
    __shared__ float sv[64];
    int t = threadIdx.x;
    for (int i = t; i < 64 * 64; i += 256) Ms[i >> 6][i & 63] = g_M[i] * (1.f / NP);
    if (t < 64) sv[t] = g_svec[t] * (1.f / NP);
    __syncthreads();

    int lane = t & 31, w = t >> 5;
    int c = blockIdx.x * 8 + w;
    float mean_p = 0.f, e2_p = 0.f;
    #pragma unroll
    for (int half = 0; half < 2; half++) {
        int bcol = lane + 32 * half;
        float wb = W2[(size_t)bcol * OUTC + c];
        mean_p = fmaf(sv[bcol], wb, mean_p);
        float p = 0.f;
        #pragma unroll 8
        for (int a = 0; a < 64; a++) {
            float wa = W2[(size_t)a * OUTC + c];
            p = fmaf(Ms[a][bcol], wa, p);
        }
        e2_p = fmaf(wb, p, e2_p);
    }
    #pragma unroll
    for (int off = 16; off > 0; off >>= 1) {
        mean_p += __shfl_xor_sync(0xFFFFFFFFu, mean_p, off);
        e2_p   += __shfl_xor_sync(0xFFFFFFFFu, e2_p, off);
    }
    if (lane == 0) {
        float var = e2_p - mean_p * mean_p;
        float s = g3[c] * rsqrtf(var + EPSV);
        g_sc3[c] = s;
        g_sh3[c] = b3[c] - mean_p * s;
    }
}

// ---------------- GEMM3 (TF32 mma) fused: out = relu(bn3(h @ W2) + x) ----------------
// grid (1250, 4): 96-row x 64-col tiles, K=64 single chunk.
__global__ void __launch_bounds__(256) k_gemm3f(const float* __restrict__ x,
                                                float* __restrict__ out) {
    __shared__ unsigned As[96][68];
    __shared__ unsigned Bs[64][72];

    int t = threadIdx.x;
    int rb = blockIdx.x * 96;
    int cb = blockIdx.y * 64;
    int lane = t & 31, w = t >> 5;
    int wr = (w & 1) * 48;
    int wc = (w >> 1) * 16;
    int f = t & 15;
    int rbase = t >> 4;
    const uint4* hbv = (const uint4*)g_hbt;
    int qr = lane >> 2, qk = lane & 3;

    // B: W2 slice [64 x 64] at col offset cb
    #pragma unroll
    for (int j = 0; j < 4; j++) {
        int c = rbase + 16 * j;
        uint4 v = *(const uint4*)&g_W2t[(size_t)c * OUTC + cb + 4 * f];
        *(uint4*)&Bs[c][4 * f] = v;
    }
    // A: h tile [96 x 64]
    #pragma unroll
    for (int j = 0; j < 6; j++) {
        int r = rbase + 16 * j;
        uint4 v = hbv[(size_t)(rb + r) * 16 + f];
        *(uint4*)&As[r][4 * f] = v;
    }
    __syncthreads();

    float acc[3][2][4] = {};
    #pragma unroll
    for (int kk = 0; kk < 64; kk += 8) {
        unsigned b[2][2];
        #pragma unroll
        for (int nt = 0; nt < 2; nt++) {
            int col = wc + nt * 8 + qr;
            b[nt][0] = Bs[kk + qk][col];
            b[nt][1] = Bs[kk + qk + 4][col];
        }
        #pragma unroll
        for (int mt = 0; mt < 3; mt++) {
            unsigned a[4];
            int ar = wr + mt * 16 + qr;
            a[0] = As[ar][kk + qk];
            a[1] = As[ar + 8][kk + qk];
            a[2] = As[ar][kk + qk + 4];
            a[3] = As[ar + 8][kk + qk + 4];
            #pragma unroll
            for (int nt = 0; nt < 2; nt++) mma_tf32(acc[mt][nt], a, b[nt]);
        }
    }

    #pragma unroll
    for (int mt = 0; mt < 3; mt++) {
        int r0 = rb + wr + mt * 16 + qr;
        #pragma unroll
        for (int nt = 0; nt < 2; nt++) {
            int c0 = cb + wc + nt * 8 + 2 * qk;
            float sce = g_sc3[c0], she = g_sh3[c0];
            float sco = g_sc3[c0 + 1], sho = g_sh3[c0 + 1];
            float2 xa = *(const float2*)&x[(size_t)r0 * OUTC + c0];
            float2 xb = *(const float2*)&x[(size_t)(r0 + 8) * OUTC + c0];
            float2 oa, ob;
            oa.x = fmaxf(fmaf(acc[mt][nt][0], sce, she) + xa.x, 0.f);
            oa.y = fmaxf(fmaf(acc[mt][nt][1], sco, sho) + xa.y, 0.f);
            ob.x = fmaxf(fmaf(acc[mt][nt][2], sce, she) + xb.x, 0.f);
            ob.y = fmaxf(fmaf(acc[mt][nt][3], sco, sho) + xb.y, 0.f);
            *(float2*)&out[(size_t)r0 * OUTC + c0] = oa;
            *(float2*)&out[(size_t)(r0 + 8) * OUTC + c0] = ob;
        }
    }
}

// ---------------- host launch ----------------
extern "C" void kernel_launch(void* const* d_in, const int* in_sizes, int n_in,
                              void* d_out, int out_size) {
    const float* x    = (const float*)d_in[0];
    const int*   nbr  = (const int*)  d_in[1];
    const float* W1   = (const float*)d_in[2];
    const float* W3   = (const float*)d_in[3];
    const float* W2   = (const float*)d_in[4];
    const float* g1   = (const float*)d_in[5];
    const float* b1   = (const float*)d_in[6];
    const float* g2   = (const float*)d_in[7];
    const float* b2   = (const float*)d_in[8];
    const float* g3   = (const float*)d_in[9];
    const float* b3   = (const float*)d_in[10];
    float* out = (float*)d_out;

    k_zero<<<16, 256>>>();
    k_wcvt<<<496, 256>>>(W3, W2);
    k_gemm1<<<NP / 96, 256>>>(x, W1);
    k_finalize<<<1, 64>>>(0, g1, b1);
    k_bn1<<<NP * MIDC / 4 / 256, 256>>>();
    k_einsum<<<NP / 96, 256>>>(nbr);
    k_stats2<<<480, 256>>>();
    k_finalize<<<1, 64>>>(1, g2, b2);
    k_moment<<<NP / 64, 256>>>();
    k_finalize3<<<32, 256>>>(W2, g3, b3);
    k_gemm3f<<<dim3(NP / 96, 4), 256>>>(x, out);
}